// round 7
// baseline (speedup 1.0000x reference)
#include <cuda_runtime.h>
#include <cuda_bf16.h>
#include <cstdint>
#include <cstddef>

#define B_  8
#define N_  2048
#define LDF 512

// ---------------- scratch (device globals: allocation-free) ----------------
__device__ __align__(16) float g_X0[B_ * N_ * 3];
__device__ __align__(16) float g_F [B_ * N_ * LDF];      // concat features [b][n][512]
__device__ __align__(16) float g_Z [B_ * N_ * LDF];      // z = W' x, rows [m][2O]
__device__ __align__(16) float g_SQ[B_ * N_];
__device__ __align__(16) int   g_ID[B_ * N_ * 4];
__device__ __align__(16) float g_WPf[512 * 128];         // packed W' fp32 (2O x C)
__device__ __align__(16) __nv_bfloat16 g_Xb[B_ * N_ * 1536];  // split activations
__device__ __align__(16) __nv_bfloat16 g_Wb[512 * 1536];      // split weights

__device__ __forceinline__ uint32_t s2u(const void* p) {
    uint32_t a;
    asm("{ .reg .u64 t; cvta.to.shared.u64 t, %1; cvt.u32.u64 %0, t; }" : "=r"(a) : "l"(p));
    return a;
}

// ---------------- transpose x (B,3,N) -> X0 [b][n][3] ----------------
__global__ void tr_x0_k(const float* __restrict__ x, float* __restrict__ X0)
{
    int t = blockIdx.x * blockDim.x + threadIdx.x;
    const int tot = B_ * 3 * N_;
    if (t >= tot) return;
    int b = t / (3 * N_);
    int r = t % (3 * N_);
    int c = r / N_;
    int n = r % N_;
    X0[((size_t)b * N_ + n) * 3 + c] = x[t];
}

// ---------------- squared norms ----------------
__global__ void sqnorm_k(const float* __restrict__ X, int ldx, int C,
                         float* __restrict__ sq)
{
    int w    = (blockIdx.x * blockDim.x + threadIdx.x) >> 5;
    int lane = threadIdx.x & 31;
    if (w >= B_ * N_) return;
    const float* r = X + (size_t)w * ldx;
    float s = 0.f;
    for (int c = lane; c < C; c += 32) { float v = r[c]; s += v * v; }
    #pragma unroll
    for (int o = 16; o; o >>= 1) s += __shfl_xor_sync(0xffffffffu, s, o);
    if (lane == 0) sq[w] = s;
}

// ---------------- top-4 insertion ----------------
__device__ __forceinline__ void top4_insert(float d, int id, float (&v)[4], int (&ix)[4])
{
    if (d > v[3] || (d == v[3] && id < ix[3])) {
        v[3] = d; ix[3] = id;
        #pragma unroll
        for (int s = 3; s > 0; s--) {
            if (v[s] > v[s-1] || (v[s] == v[s-1] && ix[s] < ix[s-1])) {
                float tv = v[s]; v[s] = v[s-1]; v[s-1] = tv;
                int   ti = ix[s]; ix[s] = ix[s-1]; ix[s-1] = ti;
            } else break;
        }
    }
}

// ---------------- fused KNN (fp32-exact), 4x8 microtile -------------------
// block 256 thr = 16(tx: 8 keys each) x 16(ty: 4 queries each)
// tile: 64 queries x 128 keys; dynamic smem pool
template<int C>
__global__ __launch_bounds__(256) void knn_kernel(const float* __restrict__ X, int ldx,
                                                  const float* __restrict__ sq,
                                                  int* __restrict__ out_idx)
{
    constexpr int CC   = (C < 32) ? C : 32;
    constexpr int QROW = 68;    // 64 + 4 pad
    constexpr int KROW = 132;   // 128 + 4 pad
    extern __shared__ __align__(16) float pool[];
    float* Qs = pool;            // [C][QROW]
    float* Ks = pool + C * QROW; // [CC][KROW]

    const int b  = blockIdx.y;
    const int q0 = blockIdx.x * 64;
    const int t  = threadIdx.x;
    const int tx = t & 15, ty = t >> 4;
    const size_t rb = (size_t)b * N_;

    // load query tile (transposed [c][m])
    if constexpr (C % 4 == 0) {
        constexpr int V = C / 4;
        for (int f = t; f < 64 * V; f += 256) {
            int cq = f % V, m = f / V;
            float4 v = *(const float4*)&X[(rb + q0 + m) * (size_t)ldx + cq * 4];
            Qs[(cq*4+0)*QROW + m] = v.x;
            Qs[(cq*4+1)*QROW + m] = v.y;
            Qs[(cq*4+2)*QROW + m] = v.z;
            Qs[(cq*4+3)*QROW + m] = v.w;
        }
    } else {
        for (int f = t; f < 64 * C; f += 256) {
            int c = f % C, m = f / C;
            Qs[c*QROW + m] = X[(rb + q0 + m) * (size_t)ldx + c];
        }
    }

    float sqq[4];
    #pragma unroll
    for (int i = 0; i < 4; i++) sqq[i] = sq[rb + q0 + ty*4 + i];

    float bv[4][4]; int bix[4][4];
    #pragma unroll
    for (int i = 0; i < 4; i++)
        #pragma unroll
        for (int j = 0; j < 4; j++) { bv[i][j] = -3.4e38f; bix[i][j] = 0x7fffffff; }

    for (int kb = 0; kb < N_; kb += 128) {
        float acc[4][8];
        #pragma unroll
        for (int i = 0; i < 4; i++)
            #pragma unroll
            for (int j = 0; j < 8; j++) acc[i][j] = 0.f;

        for (int cc = 0; cc < C; cc += CC) {
            __syncthreads();          // protect Ks (and Qs on first pass)
            if constexpr (C % 4 == 0) {
                constexpr int V = CC / 4;
                for (int f = t; f < 128 * V; f += 256) {
                    int cq = f % V, m = f / V;
                    float4 v = *(const float4*)&X[(rb + kb + m) * (size_t)ldx + cc + cq*4];
                    Ks[(cq*4+0)*KROW + m] = v.x;
                    Ks[(cq*4+1)*KROW + m] = v.y;
                    Ks[(cq*4+2)*KROW + m] = v.z;
                    Ks[(cq*4+3)*KROW + m] = v.w;
                }
            } else {
                for (int f = t; f < 128 * CC; f += 256) {
                    int c = f % CC, m = f / CC;
                    Ks[c*KROW + m] = X[(rb + kb + m) * (size_t)ldx + cc + c];
                }
            }
            __syncthreads();
            #pragma unroll
            for (int c = 0; c < CC; c++) {
                float4 q4  = *(const float4*)&Qs[(cc + c)*QROW + ty*4];
                float4 k4a = *(const float4*)&Ks[c*KROW + tx*8];
                float4 k4b = *(const float4*)&Ks[c*KROW + tx*8 + 4];
                float qa[4] = {q4.x, q4.y, q4.z, q4.w};
                float ka[8] = {k4a.x, k4a.y, k4a.z, k4a.w,
                               k4b.x, k4b.y, k4b.z, k4b.w};
                #pragma unroll
                for (int i = 0; i < 4; i++)
                    #pragma unroll
                    for (int j = 0; j < 8; j++)
                        acc[i][j] += qa[i] * ka[j];
            }
        }

        float sqk[8];
        #pragma unroll
        for (int j = 0; j < 8; j++) sqk[j] = sq[rb + kb + tx*8 + j];

        #pragma unroll
        for (int i = 0; i < 4; i++)
            #pragma unroll
            for (int j = 0; j < 8; j++) {
                float d = 2.0f * acc[i][j] - sqq[i] - sqk[j];
                top4_insert(d, kb + tx*8 + j, bv[i], bix[i]);
            }
    }

    // merge partial top-4 across the 16 tx lanes of each query
    __syncthreads();
    float* cv = pool;
    int*   ci = (int*)(pool + 64 * 64);
    #pragma unroll
    for (int qi = 0; qi < 4; qi++) {
        int base = (ty*4 + qi) * 64 + tx * 4;
        #pragma unroll
        for (int r = 0; r < 4; r++) { cv[base + r] = bv[qi][r]; ci[base + r] = bix[qi][r]; }
    }
    __syncthreads();
    if (t < 64) {
        float v4[4]; int i4[4];
        #pragma unroll
        for (int r = 0; r < 4; r++) { v4[r] = -3.4e38f; i4[r] = 0x7fffffff; }
        for (int j = 0; j < 64; j++)
            top4_insert(cv[t*64 + j], ci[t*64 + j], v4, i4);
        int* op = out_idx + (rb + q0 + t) * 4;
        op[0] = i4[0]; op[1] = i4[1]; op[2] = i4[2]; op[3] = i4[3];
    }
}

// host-side smem sizing for knn_kernel<C>
static inline int knn_smem_bytes(int C) {
    int CC = (C < 32) ? C : 32;
    int qw = C * 68, kw = CC * 132;
    int pool = qw + kw;
    if (pool < 64 * 64 * 2) pool = 64 * 64 * 2;
    return pool * 4;
}

// ---------------- pack W (O x 2C) -> W' (2O x C) ----------------
__global__ void packw_k(const float* __restrict__ W, float* __restrict__ Wp, int O, int Cc)
{
    int t = blockIdx.x * blockDim.x + threadIdx.x;
    int tot = 2 * O * Cc;
    if (t >= tot) return;
    int r = t / Cc, c = t % Cc;
    Wp[t] = (r < O) ? W[r * (2*Cc) + c] : W[(r - O) * (2*Cc) + Cc + c];
}

// ------- split fp32 -> bf16 limbs, K-expanded by term pattern --------------
__global__ void split_k(const float* __restrict__ src, int lds, int C,
                        unsigned patbits, int nT, int Kpad, int R,
                        __nv_bfloat16* __restrict__ dst)
{
    int t = blockIdx.x * blockDim.x + threadIdx.x;
    int tot = R * Kpad;
    if (t >= tot) return;
    int col = t % Kpad;
    int r   = t / Kpad;
    float v = 0.f;
    if (col < nT * C) {
        int tb = col / C, c = col - tb * C;
        float x = src[(size_t)r * lds + c];
        float h = __bfloat162float(__float2bfloat16(x));
        float m = x - h;
        int p = (patbits >> (3 * tb)) & 7;
        v = (p == 0) ? h : m;
    }
    dst[t] = __float2bfloat16(v);
}

// ---------------- SIMT NT SGEMM (precision-critical layers) ----------------
__device__ __forceinline__ void g2s_tile(float* S, const float* M, int ld,
                                         int r0, int k0, int K, int cq, int li)
{
    const float* rp = M + (size_t)(r0 + li) * ld;
    int c = k0 + cq * 4;
    float x, y, z, w;
    if (c + 3 < K && (((uintptr_t)(rp + c) & 15u) == 0)) {
        float4 v = *(const float4*)(rp + c);
        x = v.x; y = v.y; z = v.z; w = v.w;
    } else {
        x = (c + 0 < K) ? rp[c + 0] : 0.f;
        y = (c + 1 < K) ? rp[c + 1] : 0.f;
        z = (c + 2 < K) ? rp[c + 2] : 0.f;
        w = (c + 3 < K) ? rp[c + 3] : 0.f;
    }
    S[(cq*4+0)*68 + li] = x;
    S[(cq*4+1)*68 + li] = y;
    S[(cq*4+2)*68 + li] = z;
    S[(cq*4+3)*68 + li] = w;
}

__global__ __launch_bounds__(256) void gemm_nt(int K,
    const float* __restrict__ A,  int lda, size_t sA,
    const float* __restrict__ Bm, int ldb, size_t sB,
    float* __restrict__ Cm,       int ldc, size_t sC)
{
    __shared__ __align__(16) float As[16 * 68];
    __shared__ __align__(16) float Bs[16 * 68];
    const int bz = blockIdx.z;
    A  += (size_t)bz * sA;
    Bm += (size_t)bz * sB;
    Cm += (size_t)bz * sC;
    const int i0 = blockIdx.y * 64, j0 = blockIdx.x * 64;
    const int t  = threadIdx.x;
    const int tx = t & 15, ty = t >> 4;
    const int cq = t & 3,  li = t >> 2;

    float acc[4][4];
    #pragma unroll
    for (int i = 0; i < 4; i++)
        #pragma unroll
        for (int j = 0; j < 4; j++) acc[i][j] = 0.f;

    for (int k0 = 0; k0 < K; k0 += 16) {
        g2s_tile(As, A,  lda, i0, k0, K, cq, li);
        g2s_tile(Bs, Bm, ldb, j0, k0, K, cq, li);
        __syncthreads();
        #pragma unroll
        for (int c = 0; c < 16; c++) {
            float4 a4 = *(const float4*)&As[c*68 + ty*4];
            float4 b4 = *(const float4*)&Bs[c*68 + tx*4];
            float aa[4] = {a4.x, a4.y, a4.z, a4.w};
            float bb[4] = {b4.x, b4.y, b4.z, b4.w};
            #pragma unroll
            for (int i = 0; i < 4; i++)
                #pragma unroll
                for (int j = 0; j < 4; j++)
                    acc[i][j] += aa[i] * bb[j];
        }
        __syncthreads();
    }
    #pragma unroll
    for (int r = 0; r < 4; r++) {
        float4 v = make_float4(acc[r][0], acc[r][1], acc[r][2], acc[r][3]);
        *(float4*)&Cm[(size_t)(i0 + ty*4 + r) * ldc + j0 + tx*4] = v;
    }
}

// ============== HMMA bf16 NT-GEMM via mma.sync (sm_80+ path) ===============
#define KC   32
#define KPAD 8
#define AROW (KC + KPAD)

__device__ __forceinline__ void ldmx4(uint32_t (&r)[4], uint32_t addr)
{
    asm volatile("ldmatrix.sync.aligned.m8n8.x4.shared.b16 {%0,%1,%2,%3}, [%4];"
                 : "=r"(r[0]), "=r"(r[1]), "=r"(r[2]), "=r"(r[3]) : "r"(addr));
}
__device__ __forceinline__ void mma16816(float (&d)[4], const uint32_t (&a)[4],
                                         uint32_t b0, uint32_t b1)
{
    asm volatile(
        "mma.sync.aligned.m16n8k16.row.col.f32.bf16.bf16.f32 "
        "{%0,%1,%2,%3}, {%4,%5,%6,%7}, {%8,%9}, {%0,%1,%2,%3};"
        : "+f"(d[0]), "+f"(d[1]), "+f"(d[2]), "+f"(d[3])
        : "r"(a[0]), "r"(a[1]), "r"(a[2]), "r"(a[3]), "r"(b0), "r"(b1));
}

__global__ __launch_bounds__(256) void gemm_mma(int Ka,
    const __nv_bfloat16* __restrict__ A, int lda, size_t sA,
    const __nv_bfloat16* __restrict__ B, int ldb, size_t sB,
    float* __restrict__ D, int ldd, size_t sD)
{
    __shared__ __align__(16) __nv_bfloat16 As[128 * AROW];
    __shared__ __align__(16) __nv_bfloat16 Bs[128 * AROW];
    const int bz = blockIdx.z;
    A += (size_t)bz * sA;
    B += (size_t)bz * sB;
    D += (size_t)bz * sD;
    const int i0 = blockIdx.y * 128;
    const int j0 = blockIdx.x * 128;
    const int t = threadIdx.x, wid = t >> 5, lane = t & 31;
    const int wm = wid & 1, wn = wid >> 1;
    const int gid = lane >> 2, tig = lane & 3;

    const uint32_t uA = s2u(As), uB = s2u(Bs);

    const int a_r  = wm * 64 + (lane & 15);
    const int a_c8 = (lane >> 4) * 8;
    const int b_r  = wn * 32 + ((lane >> 4) << 3) + (lane & 7);
    const int b_c8 = ((lane >> 3) & 1) * 8;

    const int gr0 = t >> 2,         gc0 = (t & 3);
    const int gr1 = (t + 256) >> 2, gc1 = (t & 3);

    float acc[4][4][4];
    #pragma unroll
    for (int mt = 0; mt < 4; mt++)
        #pragma unroll
        for (int nt = 0; nt < 4; nt++)
            #pragma unroll
            for (int e = 0; e < 4; e++) acc[mt][nt][e] = 0.f;

    const int nk = Ka / KC;
    uint4 ra0, ra1, rb0, rb1;
    {
        const __nv_bfloat16* Ag = A + (size_t)i0 * lda;
        const __nv_bfloat16* Bg = B + (size_t)j0 * ldb;
        ra0 = *(const uint4*)(Ag + (size_t)gr0 * lda + gc0 * 8);
        ra1 = *(const uint4*)(Ag + (size_t)gr1 * lda + gc1 * 8);
        rb0 = *(const uint4*)(Bg + (size_t)gr0 * ldb + gc0 * 8);
        rb1 = *(const uint4*)(Bg + (size_t)gr1 * ldb + gc1 * 8);
    }

    for (int k = 0; k < nk; k++) {
        __syncthreads();
        *(uint4*)(As + gr0 * AROW + gc0 * 8) = ra0;
        *(uint4*)(As + gr1 * AROW + gc1 * 8) = ra1;
        *(uint4*)(Bs + gr0 * AROW + gc0 * 8) = rb0;
        *(uint4*)(Bs + gr1 * AROW + gc1 * 8) = rb1;
        __syncthreads();
        if (k + 1 < nk) {
            const __nv_bfloat16* Ag = A + (size_t)i0 * lda + (k + 1) * KC;
            const __nv_bfloat16* Bg = B + (size_t)j0 * ldb + (k + 1) * KC;
            ra0 = *(const uint4*)(Ag + (size_t)gr0 * lda + gc0 * 8);
            ra1 = *(const uint4*)(Ag + (size_t)gr1 * lda + gc1 * 8);
            rb0 = *(const uint4*)(Bg + (size_t)gr0 * ldb + gc0 * 8);
            rb1 = *(const uint4*)(Bg + (size_t)gr1 * ldb + gc1 * 8);
        }
        #pragma unroll
        for (int ks = 0; ks < KC; ks += 16) {
            uint32_t af[4][4], bf[2][4];
            #pragma unroll
            for (int mt = 0; mt < 4; mt++)
                ldmx4(af[mt], uA + 2u * ((a_r + mt * 16) * AROW + ks + a_c8));
            #pragma unroll
            for (int n2 = 0; n2 < 2; n2++)
                ldmx4(bf[n2], uB + 2u * ((b_r + n2 * 16) * AROW + ks + b_c8));
            #pragma unroll
            for (int mt = 0; mt < 4; mt++)
                #pragma unroll
                for (int nt = 0; nt < 4; nt++)
                    mma16816(acc[mt][nt], af[mt],
                             bf[nt >> 1][(nt & 1) * 2], bf[nt >> 1][(nt & 1) * 2 + 1]);
        }
    }

    #pragma unroll
    for (int mt = 0; mt < 4; mt++) {
        int r = i0 + wm * 64 + mt * 16 + gid;
        #pragma unroll
        for (int nt = 0; nt < 4; nt++) {
            int c = j0 + wn * 32 + nt * 8 + tig * 2;
            *(float2*)&D[(size_t)r * ldd + c]       = make_float2(acc[mt][nt][0], acc[mt][nt][1]);
            *(float2*)&D[(size_t)(r + 8) * ldd + c] = make_float2(acc[mt][nt][2], acc[mt][nt][3]);
        }
    }
}

// ---------------- gather + relu + max-over-k epilogue ---------------------
__global__ void edge_epi_k(const float* __restrict__ Z, const int* __restrict__ idx,
                           float* __restrict__ Fo, int O)
{
    const int b = blockIdx.y, n = blockIdx.x;
    const size_t rb = (size_t)b * N_;
    int4 id = *(const int4*)(idx + (rb + n) * 4);
    const size_t w = (size_t)(2 * O);
    const float* zb = Z + rb * w;
    const float* z0 = zb + (size_t)id.x * w;
    const float* z1 = zb + (size_t)id.y * w;
    const float* z2 = zb + (size_t)id.z * w;
    const float* z3 = zb + (size_t)id.w * w;
    const float* zc = zb + (size_t)n * w + O;
    float* fo = Fo + (rb + n) * LDF;
    for (int o = threadIdx.x; o < O; o += blockDim.x) {
        float m = fmaxf(fmaxf(z0[o], z1[o]), fmaxf(z2[o], z3[o]));
        fo[o] = fmaxf(m + zc[o], 0.f);
    }
}

// ---------------- orchestration ----------------
extern "C" void kernel_launch(void* const* d_in, const int* in_sizes, int n_in,
                              void* d_out, int out_size)
{
    const float* x  = (const float*)d_in[0];
    const float* W1 = (const float*)d_in[1];
    const float* W2 = (const float*)d_in[2];
    const float* W3 = (const float*)d_in[3];
    const float* W4 = (const float*)d_in[4];
    const float* W5 = (const float*)d_in[5];
    float* out = (float*)d_out;

    void* p;
    cudaGetSymbolAddress(&p, g_X0);  float* X0 = (float*)p;
    cudaGetSymbolAddress(&p, g_F );  float* F  = (float*)p;
    cudaGetSymbolAddress(&p, g_Z );  float* Z  = (float*)p;
    cudaGetSymbolAddress(&p, g_SQ);  float* SQ = (float*)p;
    cudaGetSymbolAddress(&p, g_ID);  int*   ID = (int*)p;
    cudaGetSymbolAddress(&p, g_WPf); float* WPf = (float*)p;
    cudaGetSymbolAddress(&p, g_Xb);  __nv_bfloat16* Xb = (__nv_bfloat16*)p;
    cudaGetSymbolAddress(&p, g_Wb);  __nv_bfloat16* Wb = (__nv_bfloat16*)p;

    // allow >48KB dynamic smem for the C=128 KNN
    cudaFuncSetAttribute(knn_kernel<3>,
        cudaFuncAttributeMaxDynamicSharedMemorySize, knn_smem_bytes(3));
    cudaFuncSetAttribute(knn_kernel<64>,
        cudaFuncAttributeMaxDynamicSharedMemorySize, knn_smem_bytes(64));
    cudaFuncSetAttribute(knn_kernel<128>,
        cudaFuncAttributeMaxDynamicSharedMemorySize, knn_smem_bytes(128));

    // split patterns (3-term, 2-limb): A gets {h,h,l}, B gets {h,l,h}
    const unsigned PAT_A = 0u | (0u << 3) | (1u << 6);
    const unsigned PAT_B = 0u | (1u << 3) | (0u << 6);

    tr_x0_k<<<(B_*3*N_ + 255)/256, 256>>>(x, X0);

    auto knn = [&](const float* Xin, int ldx, int C) {
        sqnorm_k<<<(B_*N_*32)/256, 256>>>(Xin, ldx, C, SQ);
        dim3 kg(N_/64, B_);
        if (C == 3)
            knn_kernel<3>  <<<kg, 256, knn_smem_bytes(3)  >>>(Xin, ldx, SQ, ID);
        else if (C == 64)
            knn_kernel<64> <<<kg, 256, knn_smem_bytes(64) >>>(Xin, ldx, SQ, ID);
        else
            knn_kernel<128><<<kg, 256, knn_smem_bytes(128)>>>(Xin, ldx, SQ, ID);
    };

    // ---- layers 1-3: SIMT fp32 z-GEMM (feeds next KNN -> stays exact)
    auto layer_simt = [&](const float* Xin, int ldx, int C, int O,
                          const float* W, float* Fout) {
        knn(Xin, ldx, C);
        int tot = 2 * O * C;
        packw_k<<<(tot + 255)/256, 256>>>(W, WPf, O, C);
        dim3 gg((2*O)/64, (B_*N_)/64, 1);
        gemm_nt<<<gg, 256>>>(C, Xin, ldx, (size_t)0, WPf, C, (size_t)0,
                             Z, 2*O, (size_t)0);
        edge_epi_k<<<dim3(N_, B_), O>>>(Z, ID, Fout, O);
    };

    layer_simt(X0,     3,   3,  64,  W1, F + 0);     // x1 -> F[:, 0:64]
    layer_simt(F + 0,  LDF, 64, 64,  W2, F + 64);    // x2 -> F[:, 64:128]
    layer_simt(F + 64, LDF, 64, 128, W3, F + 128);   // x3 -> F[:, 128:256]

    // ---- layer 4: HMMA z-GEMM (x4 only feeds the output path)
    {
        const int C = 128, O = 256, Kp = 3 * C;       // 384
        knn(F + 128, LDF, C);
        packw_k<<<(2*O*C + 255)/256, 256>>>(W4, WPf, O, C);
        split_k<<<(2*O*Kp + 255)/256, 256>>>(WPf, C, C, PAT_B, 3, Kp, 2*O, Wb);
        split_k<<<(B_*N_*Kp + 255)/256, 256>>>(F + 128, LDF, C, PAT_A, 3, Kp, B_*N_, Xb);
        dim3 gg((2*O)/128, (B_*N_)/128, 1);
        gemm_mma<<<gg, 256>>>(Kp, Xb, Kp, (size_t)0, Wb, Kp, (size_t)0,
                              Z, 2*O, (size_t)0);
        edge_epi_k<<<dim3(N_, B_), O>>>(Z, ID, F + 256, O);
    }

    // ---- final: out[b][o][n] = W5 · concat-features, HMMA
    {
        const int C = 512, Kp = 3 * C;                // 1536
        split_k<<<(512*Kp + 255)/256, 256>>>(W5, C, C, PAT_B, 3, Kp, 512, Wb);
        split_k<<<(B_*N_*Kp + 255)/256, 256>>>(F, LDF, C, PAT_A, 3, Kp, B_*N_, Xb);
        dim3 fg(N_/128, 512/128, B_);
        gemm_mma<<<fg, 256>>>(Kp,
                              Wb, Kp, (size_t)0,
                              Xb, Kp, (size_t)N_ * Kp,
                              out, N_, (size_t)512 * N_);
    }
}

// round 8
// speedup vs baseline: 1.0547x; 1.0547x over previous
#include <cuda_runtime.h>
#include <cuda_bf16.h>
#include <cstdint>
#include <cstddef>

#define B_  8
#define N_  2048
#define LDF 512

// ---------------- scratch (device globals: allocation-free) ----------------
__device__ __align__(16) float g_X0[B_ * N_ * 3];
__device__ __align__(16) float g_F [B_ * N_ * LDF];      // concat features [b][n][512]
__device__ __align__(16) float g_Z [B_ * N_ * LDF];      // z = W' x, rows [m][2O]
__device__ __align__(16) float g_SQ[B_ * N_];
__device__ __align__(16) int   g_ID[B_ * N_ * 4];
__device__ __align__(16) int   g_C8[B_ * N_ * 8];        // knn top-8 candidates
__device__ __align__(16) float g_WPf[512 * 128];         // packed W' fp32 (2O x C)
__device__ __align__(16) __nv_bfloat16 g_Xb [B_ * N_ * 1536]; // split, pattern A
__device__ __align__(16) __nv_bfloat16 g_Xb2[B_ * N_ * 384];  // split, pattern B (knn keys)
__device__ __align__(16) __nv_bfloat16 g_Wb [512 * 1536];     // split weights, pattern B

__device__ __forceinline__ uint32_t s2u(const void* p) {
    uint32_t a;
    asm("{ .reg .u64 t; cvta.to.shared.u64 t, %1; cvt.u32.u64 %0, t; }" : "=r"(a) : "l"(p));
    return a;
}

// ---------------- transpose x (B,3,N) -> X0 [b][n][3] ----------------
__global__ void tr_x0_k(const float* __restrict__ x, float* __restrict__ X0)
{
    int t = blockIdx.x * blockDim.x + threadIdx.x;
    const int tot = B_ * 3 * N_;
    if (t >= tot) return;
    int b = t / (3 * N_);
    int r = t % (3 * N_);
    int c = r / N_;
    int n = r % N_;
    X0[((size_t)b * N_ + n) * 3 + c] = x[t];
}

// ---------------- squared norms ----------------
__global__ void sqnorm_k(const float* __restrict__ X, int ldx, int C,
                         float* __restrict__ sq)
{
    int w    = (blockIdx.x * blockDim.x + threadIdx.x) >> 5;
    int lane = threadIdx.x & 31;
    if (w >= B_ * N_) return;
    const float* r = X + (size_t)w * ldx;
    float s = 0.f;
    for (int c = lane; c < C; c += 32) { float v = r[c]; s += v * v; }
    #pragma unroll
    for (int o = 16; o; o >>= 1) s += __shfl_xor_sync(0xffffffffu, s, o);
    if (lane == 0) sq[w] = s;
}

// ---------------- top-D insertion (value desc, tie: lower index) ----------
template<int D>
__device__ __forceinline__ void topD_insert(float d, int id, float (&v)[D], int (&ix)[D])
{
    if (d > v[D-1] || (d == v[D-1] && id < ix[D-1])) {
        v[D-1] = d; ix[D-1] = id;
        #pragma unroll
        for (int s = D-1; s > 0; s--) {
            if (v[s] > v[s-1] || (v[s] == v[s-1] && ix[s] < ix[s-1])) {
                float tv = v[s]; v[s] = v[s-1]; v[s-1] = tv;
                int   ti = ix[s]; ix[s] = ix[s-1]; ix[s-1] = ti;
            } else break;
        }
    }
}
__device__ __forceinline__ void top4_insert(float d, int id, float (&v)[4], int (&ix)[4])
{ topD_insert<4>(d, id, v, ix); }

// ---------------- fused KNN for C=3 (fp32-exact, R6-proven config) --------
__global__ __launch_bounds__(256) void knn3_kernel(const float* __restrict__ X,
                                                   const float* __restrict__ sq,
                                                   int* __restrict__ out_idx)
{
    constexpr int C = 3, QROW = 68;
    __shared__ __align__(16) float pool[64 * 64 * 2];
    float* Qs = pool;                  // [C][QROW]
    float* Ks = pool + C * QROW;       // [C][QROW]

    const int b  = blockIdx.y;
    const int q0 = blockIdx.x * 64;
    const int t  = threadIdx.x;
    const int tx = t & 15, ty = t >> 4;
    const size_t rb = (size_t)b * N_;

    for (int f = t; f < 64 * C; f += 256) {
        int c = f % C, m = f / C;
        Qs[c*QROW + m] = X[(rb + q0 + m) * 3 + c];
    }

    float sqq[4];
    #pragma unroll
    for (int i = 0; i < 4; i++) sqq[i] = sq[rb + q0 + ty*4 + i];

    float bv[4][4]; int bix[4][4];
    #pragma unroll
    for (int i = 0; i < 4; i++)
        #pragma unroll
        for (int j = 0; j < 4; j++) { bv[i][j] = -3.4e38f; bix[i][j] = 0x7fffffff; }

    for (int kb = 0; kb < N_; kb += 64) {
        float acc[4][4];
        #pragma unroll
        for (int i = 0; i < 4; i++)
            #pragma unroll
            for (int j = 0; j < 4; j++) acc[i][j] = 0.f;

        __syncthreads();
        for (int f = t; f < 64 * C; f += 256) {
            int c = f % C, m = f / C;
            Ks[c*QROW + m] = X[(rb + kb + m) * 3 + c];
        }
        __syncthreads();
        #pragma unroll
        for (int c = 0; c < C; c++) {
            float4 q4 = *(const float4*)&Qs[c*QROW + ty*4];
            float4 k4 = *(const float4*)&Ks[c*QROW + tx*4];
            float qa[4] = {q4.x, q4.y, q4.z, q4.w};
            float ka[4] = {k4.x, k4.y, k4.z, k4.w};
            #pragma unroll
            for (int i = 0; i < 4; i++)
                #pragma unroll
                for (int j = 0; j < 4; j++)
                    acc[i][j] += qa[i] * ka[j];
        }

        float sqk[4];
        #pragma unroll
        for (int j = 0; j < 4; j++) sqk[j] = sq[rb + kb + tx*4 + j];

        #pragma unroll
        for (int i = 0; i < 4; i++)
            #pragma unroll
            for (int j = 0; j < 4; j++) {
                float d = 2.0f * acc[i][j] - sqq[i] - sqk[j];
                top4_insert(d, kb + tx*4 + j, bv[i], bix[i]);
            }
    }

    __syncthreads();
    float* cv = pool;
    int*   ci = (int*)(pool + 64 * 64);
    #pragma unroll
    for (int qi = 0; qi < 4; qi++) {
        int base = (ty*4 + qi) * 64 + tx * 4;
        #pragma unroll
        for (int r = 0; r < 4; r++) { cv[base + r] = bv[qi][r]; ci[base + r] = bix[qi][r]; }
    }
    __syncthreads();
    if (t < 64) {
        float v4[4]; int i4[4];
        #pragma unroll
        for (int r = 0; r < 4; r++) { v4[r] = -3.4e38f; i4[r] = 0x7fffffff; }
        for (int j = 0; j < 64; j++)
            top4_insert(cv[t*64 + j], ci[t*64 + j], v4, i4);
        int* op = out_idx + (rb + q0 + t) * 4;
        op[0] = i4[0]; op[1] = i4[1]; op[2] = i4[2]; op[3] = i4[3];
    }
}

// ---------------- HMMA helpers ----------------
__device__ __forceinline__ void ldmx4(uint32_t (&r)[4], uint32_t addr)
{
    asm volatile("ldmatrix.sync.aligned.m8n8.x4.shared.b16 {%0,%1,%2,%3}, [%4];"
                 : "=r"(r[0]), "=r"(r[1]), "=r"(r[2]), "=r"(r[3]) : "r"(addr));
}
__device__ __forceinline__ void mma16816(float (&d)[4], const uint32_t (&a)[4],
                                         uint32_t b0, uint32_t b1)
{
    asm volatile(
        "mma.sync.aligned.m16n8k16.row.col.f32.bf16.bf16.f32 "
        "{%0,%1,%2,%3}, {%4,%5,%6,%7}, {%8,%9}, {%0,%1,%2,%3};"
        : "+f"(d[0]), "+f"(d[1]), "+f"(d[2]), "+f"(d[3])
        : "r"(a[0]), "r"(a[1]), "r"(a[2]), "r"(a[3]), "r"(b0), "r"(b1));
}

// ============ HMMA KNN: approx Gram (3-term split) + top-8 candidates =====
// 128 queries/block (resident split-A tile), keys swept in 128-tiles.
// 8 warps = 2(M) x 4(N); thread holds 8 rows x 8 cols per key tile.
template<int C>
__global__ __launch_bounds__(256) void knn_mma(const __nv_bfloat16* __restrict__ XA,
                                               const __nv_bfloat16* __restrict__ XB,
                                               const float* __restrict__ sq,
                                               int* __restrict__ cand)
{
    constexpr int Ka    = 3 * C;
    constexpr int AKROW = Ka + 8;     // halves; row stride mod 128B == 16B
    constexpr int BROW  = 40;         // 32 + 8 pad
    constexpr int NK    = Ka / 32;
    extern __shared__ __align__(16) float knnpool[];
    __nv_bfloat16* As = (__nv_bfloat16*)knnpool;
    __nv_bfloat16* Bs = (__nv_bfloat16*)((char*)knnpool + 128 * AKROW * 2);

    const int b  = blockIdx.y;
    const int q0 = blockIdx.x * 128;
    const size_t rb = (size_t)b * N_;
    const int t = threadIdx.x, wid = t >> 5, lane = t & 31;
    const int wm = wid & 1, wn = wid >> 1;
    const int gid = lane >> 2, tig = lane & 3;
    const uint32_t uA = s2u(As), uB = s2u(Bs);

    // resident query tile: rows q0..q0+127, Ka halves each
    for (int idx = t; idx < 128 * (Ka / 8); idx += 256) {
        int r = idx / (Ka / 8), c8 = idx % (Ka / 8);
        uint4 v = *(const uint4*)(XA + (rb + q0 + r) * (size_t)Ka + c8 * 8);
        *(uint4*)(As + r * AKROW + c8 * 8) = v;
    }
    __syncthreads();

    // fragment addressing (proven mapping from gemm_mma)
    const int a_r  = wm * 64 + (lane & 15);
    const int a_c8 = (lane >> 4) * 8;
    const int b_rl = wn * 32 + ((lane >> 4) << 3) + (lane & 7);
    const int b_c8 = ((lane >> 3) & 1) * 8;
    const int br0 = t >> 2, bc4 = t & 3;   // global->smem staging for keys

    // query norms for this thread's 8 rows
    float sqq8[8];
    #pragma unroll
    for (int i = 0; i < 8; i++) {
        int mt = i >> 1, h = i & 1;
        sqq8[i] = sq[rb + q0 + wm * 64 + mt * 16 + h * 8 + gid];
    }

    float bv[8][4]; int bix[8][4];
    #pragma unroll
    for (int i = 0; i < 8; i++)
        #pragma unroll
        for (int j = 0; j < 4; j++) { bv[i][j] = -3.4e38f; bix[i][j] = 0x7fffffff; }

    const int NT = N_ / 128;
    uint4 rk0, rk1;
    {   // prefetch tile 0, chunk 0
        const __nv_bfloat16* p = XB + rb * (size_t)Ka;
        rk0 = *(const uint4*)(p + (size_t)br0        * Ka + bc4 * 8);
        rk1 = *(const uint4*)(p + (size_t)(br0 + 64) * Ka + bc4 * 8);
    }

    for (int kt = 0; kt < NT; kt++) {
        float acc[4][4][4];
        #pragma unroll
        for (int mt = 0; mt < 4; mt++)
            #pragma unroll
            for (int nt = 0; nt < 4; nt++)
                #pragma unroll
                for (int e = 0; e < 4; e++) acc[mt][nt][e] = 0.f;

        for (int ch = 0; ch < NK; ch++) {
            __syncthreads();
            *(uint4*)(Bs + br0        * BROW + bc4 * 8) = rk0;
            *(uint4*)(Bs + (br0 + 64) * BROW + bc4 * 8) = rk1;
            __syncthreads();
            // prefetch next (chunk or next tile's chunk 0)
            int nkt = kt, nch = ch + 1;
            if (nch == NK) { nkt = kt + 1; nch = 0; }
            if (nkt < NT) {
                const __nv_bfloat16* p = XB + (rb + nkt * 128) * (size_t)Ka + nch * 32;
                rk0 = *(const uint4*)(p + (size_t)br0        * Ka + bc4 * 8);
                rk1 = *(const uint4*)(p + (size_t)(br0 + 64) * Ka + bc4 * 8);
            }
            #pragma unroll
            for (int ks = 0; ks < 32; ks += 16) {
                uint32_t af[4][4], bf[2][4];
                #pragma unroll
                for (int mt = 0; mt < 4; mt++)
                    ldmx4(af[mt], uA + 2u * ((a_r + mt * 16) * AKROW + ch * 32 + ks + a_c8));
                #pragma unroll
                for (int n2 = 0; n2 < 2; n2++)
                    ldmx4(bf[n2], uB + 2u * ((b_rl + n2 * 16) * BROW + ks + b_c8));
                #pragma unroll
                for (int mt = 0; mt < 4; mt++)
                    #pragma unroll
                    for (int nt = 0; nt < 4; nt++)
                        mma16816(acc[mt][nt], af[mt],
                                 bf[nt >> 1][(nt & 1) * 2], bf[nt >> 1][(nt & 1) * 2 + 1]);
            }
        }

        // selection for this key tile
        #pragma unroll
        for (int nt = 0; nt < 4; nt++) {
            int c0 = kt * 128 + wn * 32 + nt * 8 + tig * 2;
            float sk0 = sq[rb + c0], sk1 = sq[rb + c0 + 1];
            #pragma unroll
            for (int mt = 0; mt < 4; mt++)
                #pragma unroll
                for (int e = 0; e < 4; e++) {
                    int i8 = mt * 2 + (e >> 1);
                    float d = 2.0f * acc[mt][nt][e] - sqq8[i8] - ((e & 1) ? sk1 : sk0);
                    top4_insert(d, c0 + (e & 1), bv[i8], bix[i8]);
                }
        }
    }

    // merge: 16 threads x top4 -> top8 per row
    __syncthreads();
    float* cv = knnpool;                 // [128][64]
    int*   ci = (int*)(knnpool + 128 * 64);
    #pragma unroll
    for (int i = 0; i < 8; i++) {
        int mt = i >> 1, h = i & 1;
        int rowL = wm * 64 + mt * 16 + h * 8 + gid;
        int slot = wn * 16 + tig * 4;
        #pragma unroll
        for (int j = 0; j < 4; j++) {
            cv[rowL * 64 + slot + j] = bv[i][j];
            ci[rowL * 64 + slot + j] = bix[i][j];
        }
    }
    __syncthreads();
    if (t < 128) {
        float v8[8]; int i8[8];
        #pragma unroll
        for (int r = 0; r < 8; r++) { v8[r] = -3.4e38f; i8[r] = 0x7fffffff; }
        for (int j = 0; j < 64; j++)
            topD_insert<8>(cv[t * 64 + j], ci[t * 64 + j], v8, i8);
        int* op = cand + (rb + q0 + t) * 8;
        #pragma unroll
        for (int r = 0; r < 8; r++) op[r] = i8[r];
    }
}

static inline int knnmma_smem(int C) {
    int Ka = 3 * C, as = 128 * (Ka + 8) * 2, bs = 128 * 40 * 2;
    int tot = as + bs, mg = 128 * 64 * 8;
    return tot > mg ? tot : mg;
}

// ---- fixup: exact fp32 distances over 8 candidates -> final top-4 --------
__global__ void fixup_k(const float* __restrict__ X, int ldx, int C,
                        const float* __restrict__ sq,
                        const int* __restrict__ cand, int* __restrict__ out)
{
    int w = blockIdx.x * 8 + (threadIdx.x >> 5);
    int lane = threadIdx.x & 31;
    if (w >= B_ * N_) return;
    size_t rb = (size_t)(w >> 11) << 11;        // N_ = 2048
    int id = 0; float d = -3.4e38f;
    if (lane < 8) {
        id = cand[w * 8 + lane];
        const float* qp = X + (size_t)w * ldx;
        const float* kp = X + (rb + id) * ldx;
        float dot = 0.f;
        for (int c = 0; c < C; c += 4) {
            float4 a = *(const float4*)(qp + c);
            float4 b2 = *(const float4*)(kp + c);
            dot += a.x * b2.x + a.y * b2.y + a.z * b2.z + a.w * b2.w;
        }
        d = 2.0f * dot - sq[w] - sq[rb + id];
    }
    float v4[4]; int i4[4];
    #pragma unroll
    for (int r = 0; r < 4; r++) { v4[r] = -3.4e38f; i4[r] = 0x7fffffff; }
    #pragma unroll
    for (int j = 0; j < 8; j++) {
        float dj = __shfl_sync(0xffffffffu, d, j);
        int   ij = __shfl_sync(0xffffffffu, id, j);
        top4_insert(dj, ij, v4, i4);
    }
    if (lane == 0) {
        int4 o = make_int4(i4[0], i4[1], i4[2], i4[3]);
        *(int4*)(out + (size_t)w * 4) = o;
    }
}

// ---------------- pack W (O x 2C) -> W' (2O x C) ----------------
__global__ void packw_k(const float* __restrict__ W, float* __restrict__ Wp, int O, int Cc)
{
    int t = blockIdx.x * blockDim.x + threadIdx.x;
    int tot = 2 * O * Cc;
    if (t >= tot) return;
    int r = t / Cc, c = t % Cc;
    Wp[t] = (r < O) ? W[r * (2*Cc) + c] : W[(r - O) * (2*Cc) + Cc + c];
}

// ------- split fp32 -> bf16 limbs, K-expanded by term pattern --------------
__global__ void split_k(const float* __restrict__ src, int lds, int C,
                        unsigned patbits, int nT, int Kpad, int R,
                        __nv_bfloat16* __restrict__ dst)
{
    int t = blockIdx.x * blockDim.x + threadIdx.x;
    int tot = R * Kpad;
    if (t >= tot) return;
    int col = t % Kpad;
    int r   = t / Kpad;
    float v = 0.f;
    if (col < nT * C) {
        int tb = col / C, c = col - tb * C;
        float x = src[(size_t)r * lds + c];
        float h = __bfloat162float(__float2bfloat16(x));
        float m = x - h;
        int p = (patbits >> (3 * tb)) & 7;
        v = (p == 0) ? h : m;
    }
    dst[t] = __float2bfloat16(v);
}

// ---------------- SIMT NT SGEMM (precision-critical layers) ----------------
__device__ __forceinline__ void g2s_tile(float* S, const float* M, int ld,
                                         int r0, int k0, int K, int cq, int li)
{
    const float* rp = M + (size_t)(r0 + li) * ld;
    int c = k0 + cq * 4;
    float x, y, z, w;
    if (c + 3 < K && (((uintptr_t)(rp + c) & 15u) == 0)) {
        float4 v = *(const float4*)(rp + c);
        x = v.x; y = v.y; z = v.z; w = v.w;
    } else {
        x = (c + 0 < K) ? rp[c + 0] : 0.f;
        y = (c + 1 < K) ? rp[c + 1] : 0.f;
        z = (c + 2 < K) ? rp[c + 2] : 0.f;
        w = (c + 3 < K) ? rp[c + 3] : 0.f;
    }
    S[(cq*4+0)*68 + li] = x;
    S[(cq*4+1)*68 + li] = y;
    S[(cq*4+2)*68 + li] = z;
    S[(cq*4+3)*68 + li] = w;
}

__global__ __launch_bounds__(256) void gemm_nt(int K,
    const float* __restrict__ A,  int lda, size_t sA,
    const float* __restrict__ Bm, int ldb, size_t sB,
    float* __restrict__ Cm,       int ldc, size_t sC)
{
    __shared__ __align__(16) float As[16 * 68];
    __shared__ __align__(16) float Bs[16 * 68];
    const int bz = blockIdx.z;
    A  += (size_t)bz * sA;
    Bm += (size_t)bz * sB;
    Cm += (size_t)bz * sC;
    const int i0 = blockIdx.y * 64, j0 = blockIdx.x * 64;
    const int t  = threadIdx.x;
    const int tx = t & 15, ty = t >> 4;
    const int cq = t & 3,  li = t >> 2;

    float acc[4][4];
    #pragma unroll
    for (int i = 0; i < 4; i++)
        #pragma unroll
        for (int j = 0; j < 4; j++) acc[i][j] = 0.f;

    for (int k0 = 0; k0 < K; k0 += 16) {
        g2s_tile(As, A,  lda, i0, k0, K, cq, li);
        g2s_tile(Bs, Bm, ldb, j0, k0, K, cq, li);
        __syncthreads();
        #pragma unroll
        for (int c = 0; c < 16; c++) {
            float4 a4 = *(const float4*)&As[c*68 + ty*4];
            float4 b4 = *(const float4*)&Bs[c*68 + tx*4];
            float aa[4] = {a4.x, a4.y, a4.z, a4.w};
            float bb[4] = {b4.x, b4.y, b4.z, b4.w};
            #pragma unroll
            for (int i = 0; i < 4; i++)
                #pragma unroll
                for (int j = 0; j < 4; j++)
                    acc[i][j] += aa[i] * bb[j];
        }
        __syncthreads();
    }
    #pragma unroll
    for (int r = 0; r < 4; r++) {
        float4 v = make_float4(acc[r][0], acc[r][1], acc[r][2], acc[r][3]);
        *(float4*)&Cm[(size_t)(i0 + ty*4 + r) * ldc + j0 + tx*4] = v;
    }
}

// ============== HMMA bf16 NT-GEMM via mma.sync (proven R6 kernel) ==========
#define KC   32
#define KPAD 8
#define AROW (KC + KPAD)

__global__ __launch_bounds__(256) void gemm_mma(int Ka,
    const __nv_bfloat16* __restrict__ A, int lda, size_t sA,
    const __nv_bfloat16* __restrict__ B, int ldb, size_t sB,
    float* __restrict__ D, int ldd, size_t sD)
{
    __shared__ __align__(16) __nv_bfloat16 As[128 * AROW];
    __shared__ __align__(16) __nv_bfloat16 Bs[128 * AROW];
    const int bz = blockIdx.z;
    A += (size_t)bz * sA;
    B += (size_t)bz * sB;
    D += (size_t)bz * sD;
    const int i0 = blockIdx.y * 128;
    const int j0 = blockIdx.x * 128;
    const int t = threadIdx.x, wid = t >> 5, lane = t & 31;
    const int wm = wid & 1, wn = wid >> 1;
    const int gid = lane >> 2, tig = lane & 3;

    const uint32_t uA = s2u(As), uB = s2u(Bs);

    const int a_r  = wm * 64 + (lane & 15);
    const int a_c8 = (lane >> 4) * 8;
    const int b_r  = wn * 32 + ((lane >> 4) << 3) + (lane & 7);
    const int b_c8 = ((lane >> 3) & 1) * 8;

    const int gr0 = t >> 2,         gc0 = (t & 3);
    const int gr1 = (t + 256) >> 2, gc1 = (t & 3);

    float acc[4][4][4];
    #pragma unroll
    for (int mt = 0; mt < 4; mt++)
        #pragma unroll
        for (int nt = 0; nt < 4; nt++)
            #pragma unroll
            for (int e = 0; e < 4; e++) acc[mt][nt][e] = 0.f;

    const int nk = Ka / KC;
    uint4 ra0, ra1, rb0, rb1;
    {
        const __nv_bfloat16* Ag = A + (size_t)i0 * lda;
        const __nv_bfloat16* Bg = B + (size_t)j0 * ldb;
        ra0 = *(const uint4*)(Ag + (size_t)gr0 * lda + gc0 * 8);
        ra1 = *(const uint4*)(Ag + (size_t)gr1 * lda + gc1 * 8);
        rb0 = *(const uint4*)(Bg + (size_t)gr0 * ldb + gc0 * 8);
        rb1 = *(const uint4*)(Bg + (size_t)gr1 * ldb + gc1 * 8);
    }

    for (int k = 0; k < nk; k++) {
        __syncthreads();
        *(uint4*)(As + gr0 * AROW + gc0 * 8) = ra0;
        *(uint4*)(As + gr1 * AROW + gc1 * 8) = ra1;
        *(uint4*)(Bs + gr0 * AROW + gc0 * 8) = rb0;
        *(uint4*)(Bs + gr1 * AROW + gc1 * 8) = rb1;
        __syncthreads();
        if (k + 1 < nk) {
            const __nv_bfloat16* Ag = A + (size_t)i0 * lda + (k + 1) * KC;
            const __nv_bfloat16* Bg = B + (size_t)j0 * ldb + (k + 1) * KC;
            ra0 = *(const uint4*)(Ag + (size_t)gr0 * lda + gc0 * 8);
            ra1 = *(const uint4*)(Ag + (size_t)gr1 * lda + gc1 * 8);
            rb0 = *(const uint4*)(Bg + (size_t)gr0 * ldb + gc0 * 8);
            rb1 = *(const uint4*)(Bg + (size_t)gr1 * ldb + gc1 * 8);
        }
        #pragma unroll
        for (int ks = 0; ks < KC; ks += 16) {
            uint32_t af[4][4], bf[2][4];
            #pragma unroll
            for (int mt = 0; mt < 4; mt++)
                ldmx4(af[mt], uA + 2u * ((a_r + mt * 16) * AROW + ks + a_c8));
            #pragma unroll
            for (int n2 = 0; n2 < 2; n2++)
                ldmx4(bf[n2], uB + 2u * ((b_r + n2 * 16) * AROW + ks + b_c8));
            #pragma unroll
            for (int mt = 0; mt < 4; mt++)
                #pragma unroll
                for (int nt = 0; nt < 4; nt++)
                    mma16816(acc[mt][nt], af[mt],
                             bf[nt >> 1][(nt & 1) * 2], bf[nt >> 1][(nt & 1) * 2 + 1]);
        }
    }

    #pragma unroll
    for (int mt = 0; mt < 4; mt++) {
        int r = i0 + wm * 64 + mt * 16 + gid;
        #pragma unroll
        for (int nt = 0; nt < 4; nt++) {
            int c = j0 + wn * 32 + nt * 8 + tig * 2;
            *(float2*)&D[(size_t)r * ldd + c]       = make_float2(acc[mt][nt][0], acc[mt][nt][1]);
            *(float2*)&D[(size_t)(r + 8) * ldd + c] = make_float2(acc[mt][nt][2], acc[mt][nt][3]);
        }
    }
}

// ---------------- gather + relu + max-over-k epilogue ---------------------
__global__ void edge_epi_k(const float* __restrict__ Z, const int* __restrict__ idx,
                           float* __restrict__ Fo, int O)
{
    const int b = blockIdx.y, n = blockIdx.x;
    const size_t rb = (size_t)b * N_;
    int4 id = *(const int4*)(idx + (rb + n) * 4);
    const size_t w = (size_t)(2 * O);
    const float* zb = Z + rb * w;
    const float* z0 = zb + (size_t)id.x * w;
    const float* z1 = zb + (size_t)id.y * w;
    const float* z2 = zb + (size_t)id.z * w;
    const float* z3 = zb + (size_t)id.w * w;
    const float* zc = zb + (size_t)n * w + O;
    float* fo = Fo + (rb + n) * LDF;
    for (int o = threadIdx.x; o < O; o += blockDim.x) {
        float m = fmaxf(fmaxf(z0[o], z1[o]), fmaxf(z2[o], z3[o]));
        fo[o] = fmaxf(m + zc[o], 0.f);
    }
}

// ---------------- orchestration ----------------
extern "C" void kernel_launch(void* const* d_in, const int* in_sizes, int n_in,
                              void* d_out, int out_size)
{
    const float* x  = (const float*)d_in[0];
    const float* W1 = (const float*)d_in[1];
    const float* W2 = (const float*)d_in[2];
    const float* W3 = (const float*)d_in[3];
    const float* W4 = (const float*)d_in[4];
    const float* W5 = (const float*)d_in[5];
    float* out = (float*)d_out;

    void* p;
    cudaGetSymbolAddress(&p, g_X0);  float* X0 = (float*)p;
    cudaGetSymbolAddress(&p, g_F );  float* F  = (float*)p;
    cudaGetSymbolAddress(&p, g_Z );  float* Z  = (float*)p;
    cudaGetSymbolAddress(&p, g_SQ);  float* SQ = (float*)p;
    cudaGetSymbolAddress(&p, g_ID);  int*   ID = (int*)p;
    cudaGetSymbolAddress(&p, g_C8);  int*   C8 = (int*)p;
    cudaGetSymbolAddress(&p, g_WPf); float* WPf = (float*)p;
    cudaGetSymbolAddress(&p, g_Xb);  __nv_bfloat16* Xb  = (__nv_bfloat16*)p;
    cudaGetSymbolAddress(&p, g_Xb2); __nv_bfloat16* Xb2 = (__nv_bfloat16*)p;
    cudaGetSymbolAddress(&p, g_Wb);  __nv_bfloat16* Wb  = (__nv_bfloat16*)p;

    cudaFuncSetAttribute(knn_mma<64>,
        cudaFuncAttributeMaxDynamicSharedMemorySize, knnmma_smem(64));
    cudaFuncSetAttribute(knn_mma<128>,
        cudaFuncAttributeMaxDynamicSharedMemorySize, knnmma_smem(128));

    // split patterns (3-term, 2-limb): A gets {h,h,l}, B gets {h,l,h}
    const unsigned PAT_A = 0u | (0u << 3) | (1u << 6);
    const unsigned PAT_B = 0u | (1u << 3) | (0u << 6);

    tr_x0_k<<<(B_*3*N_ + 255)/256, 256>>>(x, X0);

    // HMMA-based knn for C in {64,128}: split -> approx top8 -> exact fixup
    auto knn_tc = [&](const float* Xin, int C) {
        int Kp = 3 * C;
        sqnorm_k<<<(B_*N_*32)/256, 256>>>(Xin, LDF, C, SQ);
        split_k<<<(B_*N_*Kp + 255)/256, 256>>>(Xin, LDF, C, PAT_A, 3, Kp, B_*N_, Xb);
        split_k<<<(B_*N_*Kp + 255)/256, 256>>>(Xin, LDF, C, PAT_B, 3, Kp, B_*N_, Xb2);
        dim3 kg(N_/128, B_);
        if (C == 64)
            knn_mma<64> <<<kg, 256, knnmma_smem(64) >>>(Xb, Xb2, SQ, C8);
        else
            knn_mma<128><<<kg, 256, knnmma_smem(128)>>>(Xb, Xb2, SQ, C8);
        fixup_k<<<(B_*N_)/8, 256>>>(Xin, LDF, C, SQ, C8, ID);
    };

    // ---- layer 1: fp32 knn (C=3) + SIMT z-GEMM
    {
        sqnorm_k<<<(B_*N_*32)/256, 256>>>(X0, 3, 3, SQ);
        knn3_kernel<<<dim3(N_/64, B_), 256>>>(X0, SQ, ID);
        packw_k<<<(2*64*3 + 255)/256, 256>>>(W1, WPf, 64, 3);
        dim3 gg(128/64, (B_*N_)/64, 1);
        gemm_nt<<<gg, 256>>>(3, X0, 3, (size_t)0, WPf, 3, (size_t)0,
                             Z, 128, (size_t)0);
        edge_epi_k<<<dim3(N_, B_), 64>>>(Z, ID, F + 0, 64);
    }

    // ---- layers 2-3: HMMA knn + SIMT fp32 z-GEMM (z feeds next knn)
    auto layer23 = [&](const float* Xin, int C, int O, const float* W, float* Fout) {
        knn_tc(Xin, C);
        packw_k<<<(2*O*C + 255)/256, 256>>>(W, WPf, O, C);
        dim3 gg((2*O)/64, (B_*N_)/64, 1);
        gemm_nt<<<gg, 256>>>(C, Xin, LDF, (size_t)0, WPf, C, (size_t)0,
                             Z, 2*O, (size_t)0);
        edge_epi_k<<<dim3(N_, B_), O>>>(Z, ID, Fout, O);
    };
    layer23(F + 0,  64, 64,  W2, F + 64);    // x2 -> F[:, 64:128]
    layer23(F + 64, 64, 128, W3, F + 128);   // x3 -> F[:, 128:256]

    // ---- layer 4: HMMA knn + HMMA z-GEMM (Xb already = PAT_A split of F+128)
    {
        const int C = 128, O = 256, Kp = 3 * C;       // 384
        knn_tc(F + 128, C);
        packw_k<<<(2*O*C + 255)/256, 256>>>(W4, WPf, O, C);
        split_k<<<(2*O*Kp + 255)/256, 256>>>(WPf, C, C, PAT_B, 3, Kp, 2*O, Wb);
        dim3 gg((2*O)/128, (B_*N_)/128, 1);
        gemm_mma<<<gg, 256>>>(Kp, Xb, Kp, (size_t)0, Wb, Kp, (size_t)0,
                              Z, 2*O, (size_t)0);
        edge_epi_k<<<dim3(N_, B_), O>>>(Z, ID, F + 256, O);
    }

    // ---- final: out[b][o][n] = W5 · concat-features, HMMA
    {
        const int C = 512, Kp = 3 * C;                // 1536
        split_k<<<(512*Kp + 255)/256, 256>>>(W5, C, C, PAT_B, 3, Kp, 512, Wb);
        split_k<<<(B_*N_*Kp + 255)/256, 256>>>(F, LDF, C, PAT_A, 3, Kp, B_*N_, Xb);
        dim3 fg(N_/128, 512/128, B_);
        gemm_mma<<<fg, 256>>>(Kp,
                              Wb, Kp, (size_t)0,
                              Xb, Kp, (size_t)N_ * Kp,
                              out, N_, (size_t)512 * N_);
    }
}

// round 9
// speedup vs baseline: 1.1239x; 1.0657x over previous
#include <cuda_runtime.h>
#include <cuda_bf16.h>
#include <cstdint>
#include <cstddef>

#define B_  8
#define N_  2048
#define LDF 512

// ---------------- scratch (device globals: allocation-free) ----------------
__device__ __align__(16) float g_X0[B_ * N_ * 3];
__device__ __align__(16) float g_F [B_ * N_ * LDF];      // concat features [b][n][512]
__device__ __align__(16) float g_Z [B_ * N_ * LDF];      // z = W' x, rows [m][2O]
__device__ __align__(16) float g_SQ[B_ * N_];
__device__ __align__(16) int   g_ID[B_ * N_ * 4];
__device__ __align__(16) int   g_C8[B_ * N_ * 8];        // knn top-8 candidates
__device__ __align__(16) float g_WPf[512 * 128];         // packed W' fp32 (2O x C)
__device__ __align__(16) __nv_bfloat16 g_Xb [B_ * N_ * 1536]; // split, pattern A
__device__ __align__(16) __nv_bfloat16 g_Xb2[B_ * N_ * 384];  // split, pattern B (knn keys)
__device__ __align__(16) __nv_bfloat16 g_Wb [512 * 1536];     // split weights, pattern B

__device__ __forceinline__ uint32_t s2u(const void* p) {
    uint32_t a;
    asm("{ .reg .u64 t; cvta.to.shared.u64 t, %1; cvt.u32.u64 %0, t; }" : "=r"(a) : "l"(p));
    return a;
}
// ---- cp.async helpers (sm_80+, valid on plain compute_103 target) --------
__device__ __forceinline__ void cp16(uint32_t dst, const void* src) {
    asm volatile("cp.async.cg.shared.global [%0], [%1], 16;" :: "r"(dst), "l"(src));
}
#define CP_COMMIT() asm volatile("cp.async.commit_group;" ::: "memory")
#define CP_WAIT1()  asm volatile("cp.async.wait_group 1;" ::: "memory")

// ---------------- transpose x (B,3,N) -> X0 [b][n][3] ----------------
__global__ void tr_x0_k(const float* __restrict__ x, float* __restrict__ X0)
{
    int t = blockIdx.x * blockDim.x + threadIdx.x;
    const int tot = B_ * 3 * N_;
    if (t >= tot) return;
    int b = t / (3 * N_);
    int r = t % (3 * N_);
    int c = r / N_;
    int n = r % N_;
    X0[((size_t)b * N_ + n) * 3 + c] = x[t];
}

// ---------------- squared norms ----------------
__global__ void sqnorm_k(const float* __restrict__ X, int ldx, int C,
                         float* __restrict__ sq)
{
    int w    = (blockIdx.x * blockDim.x + threadIdx.x) >> 5;
    int lane = threadIdx.x & 31;
    if (w >= B_ * N_) return;
    const float* r = X + (size_t)w * ldx;
    float s = 0.f;
    for (int c = lane; c < C; c += 32) { float v = r[c]; s += v * v; }
    #pragma unroll
    for (int o = 16; o; o >>= 1) s += __shfl_xor_sync(0xffffffffu, s, o);
    if (lane == 0) sq[w] = s;
}

// ---------------- top-D insertion (value desc, tie: lower index) ----------
template<int D>
__device__ __forceinline__ void topD_insert(float d, int id, float (&v)[D], int (&ix)[D])
{
    if (d > v[D-1] || (d == v[D-1] && id < ix[D-1])) {
        v[D-1] = d; ix[D-1] = id;
        #pragma unroll
        for (int s = D-1; s > 0; s--) {
            if (v[s] > v[s-1] || (v[s] == v[s-1] && ix[s] < ix[s-1])) {
                float tv = v[s]; v[s] = v[s-1]; v[s-1] = tv;
                int   ti = ix[s]; ix[s] = ix[s-1]; ix[s-1] = ti;
            } else break;
        }
    }
}
__device__ __forceinline__ void top4_insert(float d, int id, float (&v)[4], int (&ix)[4])
{ topD_insert<4>(d, id, v, ix); }

// ---------------- fused KNN for C=3 (fp32-exact) --------------------------
__global__ __launch_bounds__(256) void knn3_kernel(const float* __restrict__ X,
                                                   const float* __restrict__ sq,
                                                   int* __restrict__ out_idx)
{
    constexpr int C = 3, QROW = 68;
    __shared__ __align__(16) float pool[64 * 64 * 2];
    float* Qs = pool;
    float* Ks = pool + C * QROW;

    const int b  = blockIdx.y;
    const int q0 = blockIdx.x * 64;
    const int t  = threadIdx.x;
    const int tx = t & 15, ty = t >> 4;
    const size_t rb = (size_t)b * N_;

    for (int f = t; f < 64 * C; f += 256) {
        int c = f % C, m = f / C;
        Qs[c*QROW + m] = X[(rb + q0 + m) * 3 + c];
    }

    float sqq[4];
    #pragma unroll
    for (int i = 0; i < 4; i++) sqq[i] = sq[rb + q0 + ty*4 + i];

    float bv[4][4]; int bix[4][4];
    #pragma unroll
    for (int i = 0; i < 4; i++)
        #pragma unroll
        for (int j = 0; j < 4; j++) { bv[i][j] = -3.4e38f; bix[i][j] = 0x7fffffff; }

    for (int kb = 0; kb < N_; kb += 64) {
        float acc[4][4];
        #pragma unroll
        for (int i = 0; i < 4; i++)
            #pragma unroll
            for (int j = 0; j < 4; j++) acc[i][j] = 0.f;

        __syncthreads();
        for (int f = t; f < 64 * C; f += 256) {
            int c = f % C, m = f / C;
            Ks[c*QROW + m] = X[(rb + kb + m) * 3 + c];
        }
        __syncthreads();
        #pragma unroll
        for (int c = 0; c < C; c++) {
            float4 q4 = *(const float4*)&Qs[c*QROW + ty*4];
            float4 k4 = *(const float4*)&Ks[c*QROW + tx*4];
            float qa[4] = {q4.x, q4.y, q4.z, q4.w};
            float ka[4] = {k4.x, k4.y, k4.z, k4.w};
            #pragma unroll
            for (int i = 0; i < 4; i++)
                #pragma unroll
                for (int j = 0; j < 4; j++)
                    acc[i][j] += qa[i] * ka[j];
        }

        float sqk[4];
        #pragma unroll
        for (int j = 0; j < 4; j++) sqk[j] = sq[rb + kb + tx*4 + j];

        #pragma unroll
        for (int i = 0; i < 4; i++)
            #pragma unroll
            for (int j = 0; j < 4; j++) {
                float d = 2.0f * acc[i][j] - sqq[i] - sqk[j];
                top4_insert(d, kb + tx*4 + j, bv[i], bix[i]);
            }
    }

    __syncthreads();
    float* cv = pool;
    int*   ci = (int*)(pool + 64 * 64);
    #pragma unroll
    for (int qi = 0; qi < 4; qi++) {
        int base = (ty*4 + qi) * 64 + tx * 4;
        #pragma unroll
        for (int r = 0; r < 4; r++) { cv[base + r] = bv[qi][r]; ci[base + r] = bix[qi][r]; }
    }
    __syncthreads();
    if (t < 64) {
        float v4[4]; int i4[4];
        #pragma unroll
        for (int r = 0; r < 4; r++) { v4[r] = -3.4e38f; i4[r] = 0x7fffffff; }
        for (int j = 0; j < 64; j++)
            top4_insert(cv[t*64 + j], ci[t*64 + j], v4, i4);
        int* op = out_idx + (rb + q0 + t) * 4;
        op[0] = i4[0]; op[1] = i4[1]; op[2] = i4[2]; op[3] = i4[3];
    }
}

// ---------------- HMMA helpers ----------------
__device__ __forceinline__ void ldmx4(uint32_t (&r)[4], uint32_t addr)
{
    asm volatile("ldmatrix.sync.aligned.m8n8.x4.shared.b16 {%0,%1,%2,%3}, [%4];"
                 : "=r"(r[0]), "=r"(r[1]), "=r"(r[2]), "=r"(r[3]) : "r"(addr));
}
__device__ __forceinline__ void mma16816(float (&d)[4], const uint32_t (&a)[4],
                                         uint32_t b0, uint32_t b1)
{
    asm volatile(
        "mma.sync.aligned.m16n8k16.row.col.f32.bf16.bf16.f32 "
        "{%0,%1,%2,%3}, {%4,%5,%6,%7}, {%8,%9}, {%0,%1,%2,%3};"
        : "+f"(d[0]), "+f"(d[1]), "+f"(d[2]), "+f"(d[3])
        : "r"(a[0]), "r"(a[1]), "r"(a[2]), "r"(a[3]), "r"(b0), "r"(b1));
}

// ============ HMMA KNN: approx Gram + top-8, cp.async 3-stage keys ========
template<int C>
__global__ __launch_bounds__(256) void knn_mma(const __nv_bfloat16* __restrict__ XA,
                                               const __nv_bfloat16* __restrict__ XB,
                                               const float* __restrict__ sq,
                                               int* __restrict__ cand)
{
    constexpr int Ka    = 3 * C;
    constexpr int AKROW = Ka + 8;
    constexpr int BROW  = 40;          // 32 + 8 pad
    constexpr int BSTG  = 128 * BROW;  // halves per key stage
    constexpr int NK    = Ka / 32;
    constexpr int NT    = N_ / 128;
    constexpr int NCH   = NT * NK;
    extern __shared__ __align__(16) float knnpool[];
    __nv_bfloat16* As = (__nv_bfloat16*)knnpool;
    __nv_bfloat16* Bs = (__nv_bfloat16*)((char*)knnpool + 128 * AKROW * 2);

    const int b  = blockIdx.y;
    const int q0 = blockIdx.x * 128;
    const size_t rb = (size_t)b * N_;
    const int t = threadIdx.x, wid = t >> 5, lane = t & 31;
    const int wm = wid & 1, wn = wid >> 1;
    const int gid = lane >> 2, tig = lane & 3;
    const uint32_t uA = s2u(As), uB = s2u(Bs);

    // resident query tile
    for (int idx = t; idx < 128 * (Ka / 8); idx += 256) {
        int r = idx / (Ka / 8), c8 = idx % (Ka / 8);
        uint4 v = *(const uint4*)(XA + (rb + q0 + r) * (size_t)Ka + c8 * 8);
        *(uint4*)(As + r * AKROW + c8 * 8) = v;
    }
    __syncthreads();

    const int a_r  = wm * 64 + (lane & 15);
    const int a_c8 = (lane >> 4) * 8;
    const int b_rl = wn * 32 + ((lane >> 4) << 3) + (lane & 7);
    const int b_c8 = ((lane >> 3) & 1) * 8;
    const int br0 = t >> 2, bc4 = t & 3;

    float sqq8[8];
    #pragma unroll
    for (int i = 0; i < 8; i++) {
        int mt = i >> 1, h = i & 1;
        sqq8[i] = sq[rb + q0 + wm * 64 + mt * 16 + h * 8 + gid];
    }

    float bv[8][4]; int bix[8][4];
    #pragma unroll
    for (int i = 0; i < 8; i++)
        #pragma unroll
        for (int j = 0; j < 4; j++) { bv[i][j] = -3.4e38f; bix[i][j] = 0x7fffffff; }

    auto kissue = [&](int cc2) {
        if (cc2 < NCH) {
            int kt2 = cc2 / NK, ch2 = cc2 % NK;
            int s = cc2 % 3;
            const __nv_bfloat16* p = XB + (rb + kt2 * 128) * (size_t)Ka + ch2 * 32;
            uint32_t db = uB + 2u * (s * BSTG);
            cp16(db + 2u * (br0 * BROW + bc4 * 8),
                 p + (size_t)br0 * Ka + bc4 * 8);
            cp16(db + 2u * ((br0 + 64) * BROW + bc4 * 8),
                 p + (size_t)(br0 + 64) * Ka + bc4 * 8);
        }
        CP_COMMIT();
    };

    kissue(0); kissue(1);
    int cc = 0;
    for (int kt = 0; kt < NT; kt++) {
        float acc[4][4][4];
        #pragma unroll
        for (int mt = 0; mt < 4; mt++)
            #pragma unroll
            for (int nt = 0; nt < 4; nt++)
                #pragma unroll
                for (int e = 0; e < 4; e++) acc[mt][nt][e] = 0.f;

        for (int ch = 0; ch < NK; ch++) {
            CP_WAIT1();
            __syncthreads();
            const uint32_t uBs = uB + 2u * ((cc % 3) * BSTG);
            #pragma unroll
            for (int ks = 0; ks < 32; ks += 16) {
                uint32_t af[4][4], bf[2][4];
                #pragma unroll
                for (int mt = 0; mt < 4; mt++)
                    ldmx4(af[mt], uA + 2u * ((a_r + mt * 16) * AKROW + ch * 32 + ks + a_c8));
                #pragma unroll
                for (int n2 = 0; n2 < 2; n2++)
                    ldmx4(bf[n2], uBs + 2u * ((b_rl + n2 * 16) * BROW + ks + b_c8));
                #pragma unroll
                for (int mt = 0; mt < 4; mt++)
                    #pragma unroll
                    for (int nt = 0; nt < 4; nt++)
                        mma16816(acc[mt][nt], af[mt],
                                 bf[nt >> 1][(nt & 1) * 2], bf[nt >> 1][(nt & 1) * 2 + 1]);
            }
            kissue(cc + 2);
            cc++;
        }

        // selection for this key tile
        #pragma unroll
        for (int nt = 0; nt < 4; nt++) {
            int c0 = kt * 128 + wn * 32 + nt * 8 + tig * 2;
            float sk0 = sq[rb + c0], sk1 = sq[rb + c0 + 1];
            #pragma unroll
            for (int mt = 0; mt < 4; mt++)
                #pragma unroll
                for (int e = 0; e < 4; e++) {
                    int i8 = mt * 2 + (e >> 1);
                    float d = 2.0f * acc[mt][nt][e] - sqq8[i8] - ((e & 1) ? sk1 : sk0);
                    top4_insert(d, c0 + (e & 1), bv[i8], bix[i8]);
                }
        }
    }

    // merge: 16 threads x top4 -> top8 per row
    __syncthreads();
    float* cv = knnpool;
    int*   ci = (int*)(knnpool + 128 * 64);
    #pragma unroll
    for (int i = 0; i < 8; i++) {
        int mt = i >> 1, h = i & 1;
        int rowL = wm * 64 + mt * 16 + h * 8 + gid;
        int slot = wn * 16 + tig * 4;
        #pragma unroll
        for (int j = 0; j < 4; j++) {
            cv[rowL * 64 + slot + j] = bv[i][j];
            ci[rowL * 64 + slot + j] = bix[i][j];
        }
    }
    __syncthreads();
    if (t < 128) {
        float v8[8]; int i8[8];
        #pragma unroll
        for (int r = 0; r < 8; r++) { v8[r] = -3.4e38f; i8[r] = 0x7fffffff; }
        for (int j = 0; j < 64; j++)
            topD_insert<8>(cv[t * 64 + j], ci[t * 64 + j], v8, i8);
        int* op = cand + (rb + q0 + t) * 8;
        #pragma unroll
        for (int r = 0; r < 8; r++) op[r] = i8[r];
    }
}

static inline int knnmma_smem(int C) {
    int Ka = 3 * C;
    int as = 128 * (Ka + 8) * 2;
    int bs = 3 * 128 * 40 * 2;
    int tot = as + bs, mg = 128 * 64 * 8;
    return tot > mg ? tot : mg;
}

// ---- fixup: exact fp32 distances over 8 candidates -> final top-4 --------
__global__ void fixup_k(const float* __restrict__ X, int ldx, int C,
                        const float* __restrict__ sq,
                        const int* __restrict__ cand, int* __restrict__ out)
{
    int w = blockIdx.x * 8 + (threadIdx.x >> 5);
    int lane = threadIdx.x & 31;
    if (w >= B_ * N_) return;
    size_t rb = (size_t)(w >> 11) << 11;        // N_ = 2048
    int id = 0; float d = -3.4e38f;
    if (lane < 8) {
        id = cand[w * 8 + lane];
        const float* qp = X + (size_t)w * ldx;
        const float* kp = X + (rb + id) * ldx;
        float dot = 0.f;
        for (int c = 0; c < C; c += 4) {
            float4 a = *(const float4*)(qp + c);
            float4 b2 = *(const float4*)(kp + c);
            dot += a.x * b2.x + a.y * b2.y + a.z * b2.z + a.w * b2.w;
        }
        d = 2.0f * dot - sq[w] - sq[rb + id];
    }
    float v4[4]; int i4[4];
    #pragma unroll
    for (int r = 0; r < 4; r++) { v4[r] = -3.4e38f; i4[r] = 0x7fffffff; }
    #pragma unroll
    for (int j = 0; j < 8; j++) {
        float dj = __shfl_sync(0xffffffffu, d, j);
        int   ij = __shfl_sync(0xffffffffu, id, j);
        top4_insert(dj, ij, v4, i4);
    }
    if (lane == 0) {
        int4 o = make_int4(i4[0], i4[1], i4[2], i4[3]);
        *(int4*)(out + (size_t)w * 4) = o;
    }
}

// ---------------- pack W (O x 2C) -> W' (2O x C) ----------------
__global__ void packw_k(const float* __restrict__ W, float* __restrict__ Wp, int O, int Cc)
{
    int t = blockIdx.x * blockDim.x + threadIdx.x;
    int tot = 2 * O * Cc;
    if (t >= tot) return;
    int r = t / Cc, c = t % Cc;
    Wp[t] = (r < O) ? W[r * (2*Cc) + c] : W[(r - O) * (2*Cc) + Cc + c];
}

// ------- split fp32 -> bf16 limbs, K-expanded by term pattern --------------
__global__ void split_k(const float* __restrict__ src, int lds, int C,
                        unsigned patbits, int nT, int Kpad, int R,
                        __nv_bfloat16* __restrict__ dst)
{
    int t = blockIdx.x * blockDim.x + threadIdx.x;
    int tot = R * Kpad;
    if (t >= tot) return;
    int col = t % Kpad;
    int r   = t / Kpad;
    float v = 0.f;
    if (col < nT * C) {
        int tb = col / C, c = col - tb * C;
        float x = src[(size_t)r * lds + c];
        float h = __bfloat162float(__float2bfloat16(x));
        float m = x - h;
        int p = (patbits >> (3 * tb)) & 7;
        v = (p == 0) ? h : m;
    }
    dst[t] = __float2bfloat16(v);
}

// ---------------- SIMT NT SGEMM (precision-critical layers) ----------------
__device__ __forceinline__ void g2s_tile(float* S, const float* M, int ld,
                                         int r0, int k0, int K, int cq, int li)
{
    const float* rp = M + (size_t)(r0 + li) * ld;
    int c = k0 + cq * 4;
    float x, y, z, w;
    if (c + 3 < K && (((uintptr_t)(rp + c) & 15u) == 0)) {
        float4 v = *(const float4*)(rp + c);
        x = v.x; y = v.y; z = v.z; w = v.w;
    } else {
        x = (c + 0 < K) ? rp[c + 0] : 0.f;
        y = (c + 1 < K) ? rp[c + 1] : 0.f;
        z = (c + 2 < K) ? rp[c + 2] : 0.f;
        w = (c + 3 < K) ? rp[c + 3] : 0.f;
    }
    S[(cq*4+0)*68 + li] = x;
    S[(cq*4+1)*68 + li] = y;
    S[(cq*4+2)*68 + li] = z;
    S[(cq*4+3)*68 + li] = w;
}

__global__ __launch_bounds__(256) void gemm_nt(int K,
    const float* __restrict__ A,  int lda, size_t sA,
    const float* __restrict__ Bm, int ldb, size_t sB,
    float* __restrict__ Cm,       int ldc, size_t sC)
{
    __shared__ __align__(16) float As[16 * 68];
    __shared__ __align__(16) float Bs[16 * 68];
    const int bz = blockIdx.z;
    A  += (size_t)bz * sA;
    Bm += (size_t)bz * sB;
    Cm += (size_t)bz * sC;
    const int i0 = blockIdx.y * 64, j0 = blockIdx.x * 64;
    const int t  = threadIdx.x;
    const int tx = t & 15, ty = t >> 4;
    const int cq = t & 3,  li = t >> 2;

    float acc[4][4];
    #pragma unroll
    for (int i = 0; i < 4; i++)
        #pragma unroll
        for (int j = 0; j < 4; j++) acc[i][j] = 0.f;

    for (int k0 = 0; k0 < K; k0 += 16) {
        g2s_tile(As, A,  lda, i0, k0, K, cq, li);
        g2s_tile(Bs, Bm, ldb, j0, k0, K, cq, li);
        __syncthreads();
        #pragma unroll
        for (int c = 0; c < 16; c++) {
            float4 a4 = *(const float4*)&As[c*68 + ty*4];
            float4 b4 = *(const float4*)&Bs[c*68 + tx*4];
            float aa[4] = {a4.x, a4.y, a4.z, a4.w};
            float bb[4] = {b4.x, b4.y, b4.z, b4.w};
            #pragma unroll
            for (int i = 0; i < 4; i++)
                #pragma unroll
                for (int j = 0; j < 4; j++)
                    acc[i][j] += aa[i] * bb[j];
        }
        __syncthreads();
    }
    #pragma unroll
    for (int r = 0; r < 4; r++) {
        float4 v = make_float4(acc[r][0], acc[r][1], acc[r][2], acc[r][3]);
        *(float4*)&Cm[(size_t)(i0 + ty*4 + r) * ldc + j0 + tx*4] = v;
    }
}

// ============== HMMA bf16 NT-GEMM, cp.async 3-stage pipeline ===============
#define KC   32
#define KPAD 8
#define AROW (KC + KPAD)
#define GSTG (128 * AROW)                     // halves per stage per operand
#define GSMEM (3 * GSTG * 2 * 2)              // bytes: 3 stages x (A+B)

__global__ __launch_bounds__(256) void gemm_mma(int Ka,
    const __nv_bfloat16* __restrict__ A, int lda, size_t sA,
    const __nv_bfloat16* __restrict__ B, int ldb, size_t sB,
    float* __restrict__ D, int ldd, size_t sD)
{
    extern __shared__ __align__(16) __nv_bfloat16 gsm[];
    __nv_bfloat16* As = gsm;                  // [3][GSTG]
    __nv_bfloat16* Bs = gsm + 3 * GSTG;       // [3][GSTG]
    const int bz = blockIdx.z;
    A += (size_t)bz * sA;
    B += (size_t)bz * sB;
    D += (size_t)bz * sD;
    const int i0 = blockIdx.y * 128;
    const int j0 = blockIdx.x * 128;
    const int t = threadIdx.x, wid = t >> 5, lane = t & 31;
    const int wm = wid & 1, wn = wid >> 1;
    const int gid = lane >> 2, tig = lane & 3;

    const uint32_t uA = s2u(As), uB = s2u(Bs);

    const int a_r  = wm * 64 + (lane & 15);
    const int a_c8 = (lane >> 4) * 8;
    const int b_r  = wn * 32 + ((lane >> 4) << 3) + (lane & 7);
    const int b_c8 = ((lane >> 3) & 1) * 8;

    const int gr0 = t >> 2, gc0 = t & 3;
    const int gr1 = gr0 + 64;

    float acc[4][4][4];
    #pragma unroll
    for (int mt = 0; mt < 4; mt++)
        #pragma unroll
        for (int nt = 0; nt < 4; nt++)
            #pragma unroll
            for (int e = 0; e < 4; e++) acc[mt][nt][e] = 0.f;

    const int nk = Ka / KC;

    auto issue = [&](int k2) {
        if (k2 < nk) {
            int s = k2 % 3;
            const __nv_bfloat16* Ag = A + (size_t)i0 * lda + k2 * KC;
            const __nv_bfloat16* Bg = B + (size_t)j0 * ldb + k2 * KC;
            uint32_t da = uA + 2u * (s * GSTG);
            uint32_t db = uB + 2u * (s * GSTG);
            cp16(da + 2u * (gr0 * AROW + gc0 * 8), Ag + (size_t)gr0 * lda + gc0 * 8);
            cp16(da + 2u * (gr1 * AROW + gc0 * 8), Ag + (size_t)gr1 * lda + gc0 * 8);
            cp16(db + 2u * (gr0 * AROW + gc0 * 8), Bg + (size_t)gr0 * ldb + gc0 * 8);
            cp16(db + 2u * (gr1 * AROW + gc0 * 8), Bg + (size_t)gr1 * ldb + gc0 * 8);
        }
        CP_COMMIT();
    };

    issue(0); issue(1);
    for (int k = 0; k < nk; k++) {
        CP_WAIT1();
        __syncthreads();
        const int s = k % 3;
        const uint32_t uAs = uA + 2u * (s * GSTG);
        const uint32_t uBs = uB + 2u * (s * GSTG);
        #pragma unroll
        for (int ks = 0; ks < KC; ks += 16) {
            uint32_t af[4][4], bf[2][4];
            #pragma unroll
            for (int mt = 0; mt < 4; mt++)
                ldmx4(af[mt], uAs + 2u * ((a_r + mt * 16) * AROW + ks + a_c8));
            #pragma unroll
            for (int n2 = 0; n2 < 2; n2++)
                ldmx4(bf[n2], uBs + 2u * ((b_r + n2 * 16) * AROW + ks + b_c8));
            #pragma unroll
            for (int mt = 0; mt < 4; mt++)
                #pragma unroll
                for (int nt = 0; nt < 4; nt++)
                    mma16816(acc[mt][nt], af[mt],
                             bf[nt >> 1][(nt & 1) * 2], bf[nt >> 1][(nt & 1) * 2 + 1]);
        }
        issue(k + 2);
    }

    #pragma unroll
    for (int mt = 0; mt < 4; mt++) {
        int r = i0 + wm * 64 + mt * 16 + gid;
        #pragma unroll
        for (int nt = 0; nt < 4; nt++) {
            int c = j0 + wn * 32 + nt * 8 + tig * 2;
            *(float2*)&D[(size_t)r * ldd + c]       = make_float2(acc[mt][nt][0], acc[mt][nt][1]);
            *(float2*)&D[(size_t)(r + 8) * ldd + c] = make_float2(acc[mt][nt][2], acc[mt][nt][3]);
        }
    }
}

// ---------------- gather + relu + max-over-k epilogue ---------------------
__global__ void edge_epi_k(const float* __restrict__ Z, const int* __restrict__ idx,
                           float* __restrict__ Fo, int O)
{
    const int b = blockIdx.y, n = blockIdx.x;
    const size_t rb = (size_t)b * N_;
    int4 id = *(const int4*)(idx + (rb + n) * 4);
    const size_t w = (size_t)(2 * O);
    const float* zb = Z + rb * w;
    const float* z0 = zb + (size_t)id.x * w;
    const float* z1 = zb + (size_t)id.y * w;
    const float* z2 = zb + (size_t)id.z * w;
    const float* z3 = zb + (size_t)id.w * w;
    const float* zc = zb + (size_t)n * w + O;
    float* fo = Fo + (rb + n) * LDF;
    for (int o = threadIdx.x; o < O; o += blockDim.x) {
        float m = fmaxf(fmaxf(z0[o], z1[o]), fmaxf(z2[o], z3[o]));
        fo[o] = fmaxf(m + zc[o], 0.f);
    }
}

// ---------------- orchestration ----------------
extern "C" void kernel_launch(void* const* d_in, const int* in_sizes, int n_in,
                              void* d_out, int out_size)
{
    const float* x  = (const float*)d_in[0];
    const float* W1 = (const float*)d_in[1];
    const float* W2 = (const float*)d_in[2];
    const float* W3 = (const float*)d_in[3];
    const float* W4 = (const float*)d_in[4];
    const float* W5 = (const float*)d_in[5];
    float* out = (float*)d_out;

    void* p;
    cudaGetSymbolAddress(&p, g_X0);  float* X0 = (float*)p;
    cudaGetSymbolAddress(&p, g_F );  float* F  = (float*)p;
    cudaGetSymbolAddress(&p, g_Z );  float* Z  = (float*)p;
    cudaGetSymbolAddress(&p, g_SQ);  float* SQ = (float*)p;
    cudaGetSymbolAddress(&p, g_ID);  int*   ID = (int*)p;
    cudaGetSymbolAddress(&p, g_C8);  int*   C8 = (int*)p;
    cudaGetSymbolAddress(&p, g_WPf); float* WPf = (float*)p;
    cudaGetSymbolAddress(&p, g_Xb);  __nv_bfloat16* Xb  = (__nv_bfloat16*)p;
    cudaGetSymbolAddress(&p, g_Xb2); __nv_bfloat16* Xb2 = (__nv_bfloat16*)p;
    cudaGetSymbolAddress(&p, g_Wb);  __nv_bfloat16* Wb  = (__nv_bfloat16*)p;

    cudaFuncSetAttribute(knn_mma<64>,
        cudaFuncAttributeMaxDynamicSharedMemorySize, knnmma_smem(64));
    cudaFuncSetAttribute(knn_mma<128>,
        cudaFuncAttributeMaxDynamicSharedMemorySize, knnmma_smem(128));
    cudaFuncSetAttribute(gemm_mma,
        cudaFuncAttributeMaxDynamicSharedMemorySize, GSMEM);

    // split patterns (3-term, 2-limb): A gets {h,h,l}, B gets {h,l,h}
    const unsigned PAT_A = 0u | (0u << 3) | (1u << 6);
    const unsigned PAT_B = 0u | (1u << 3) | (0u << 6);

    tr_x0_k<<<(B_*3*N_ + 255)/256, 256>>>(x, X0);

    // HMMA-based knn for C in {64,128}: split -> approx top8 -> exact fixup
    auto knn_tc = [&](const float* Xin, int C) {
        int Kp = 3 * C;
        sqnorm_k<<<(B_*N_*32)/256, 256>>>(Xin, LDF, C, SQ);
        split_k<<<(B_*N_*Kp + 255)/256, 256>>>(Xin, LDF, C, PAT_A, 3, Kp, B_*N_, Xb);
        split_k<<<(B_*N_*Kp + 255)/256, 256>>>(Xin, LDF, C, PAT_B, 3, Kp, B_*N_, Xb2);
        dim3 kg(N_/128, B_);
        if (C == 64)
            knn_mma<64> <<<kg, 256, knnmma_smem(64) >>>(Xb, Xb2, SQ, C8);
        else
            knn_mma<128><<<kg, 256, knnmma_smem(128)>>>(Xb, Xb2, SQ, C8);
        fixup_k<<<(B_*N_)/8, 256>>>(Xin, LDF, C, SQ, C8, ID);
    };

    // ---- layer 1: fp32 knn (C=3) + SIMT z-GEMM
    {
        sqnorm_k<<<(B_*N_*32)/256, 256>>>(X0, 3, 3, SQ);
        knn3_kernel<<<dim3(N_/64, B_), 256>>>(X0, SQ, ID);
        packw_k<<<(2*64*3 + 255)/256, 256>>>(W1, WPf, 64, 3);
        dim3 gg(128/64, (B_*N_)/64, 1);
        gemm_nt<<<gg, 256>>>(3, X0, 3, (size_t)0, WPf, 3, (size_t)0,
                             Z, 128, (size_t)0);
        edge_epi_k<<<dim3(N_, B_), 64>>>(Z, ID, F + 0, 64);
    }

    // ---- layers 2-3: HMMA knn + SIMT fp32 z-GEMM (z feeds next knn)
    auto layer23 = [&](const float* Xin, int C, int O, const float* W, float* Fout) {
        knn_tc(Xin, C);
        packw_k<<<(2*O*C + 255)/256, 256>>>(W, WPf, O, C);
        dim3 gg((2*O)/64, (B_*N_)/64, 1);
        gemm_nt<<<gg, 256>>>(C, Xin, LDF, (size_t)0, WPf, C, (size_t)0,
                             Z, 2*O, (size_t)0);
        edge_epi_k<<<dim3(N_, B_), O>>>(Z, ID, Fout, O);
    };
    layer23(F + 0,  64, 64,  W2, F + 64);    // x2 -> F[:, 64:128]
    layer23(F + 64, 64, 128, W3, F + 128);   // x3 -> F[:, 128:256]

    // ---- layer 4: HMMA knn + HMMA z-GEMM (Xb already = PAT_A split of F+128)
    {
        const int C = 128, O = 256, Kp = 3 * C;       // 384
        knn_tc(F + 128, C);
        packw_k<<<(2*O*C + 255)/256, 256>>>(W4, WPf, O, C);
        split_k<<<(2*O*Kp + 255)/256, 256>>>(WPf, C, C, PAT_B, 3, Kp, 2*O, Wb);
        dim3 gg((2*O)/128, (B_*N_)/128, 1);
        gemm_mma<<<gg, 256, GSMEM>>>(Kp, Xb, Kp, (size_t)0, Wb, Kp, (size_t)0,
                                     Z, 2*O, (size_t)0);
        edge_epi_k<<<dim3(N_, B_), O>>>(Z, ID, F + 256, O);
    }

    // ---- final: out[b][o][n] = W5 · concat-features, HMMA
    {
        const int C = 512, Kp = 3 * C;                // 1536
        split_k<<<(512*Kp + 255)/256, 256>>>(W5, C, C, PAT_B, 3, Kp, 512, Wb);
        split_k<<<(B_*N_*Kp + 255)/256, 256>>>(F, LDF, C, PAT_A, 3, Kp, B_*N_, Xb);
        dim3 fg(N_/128, 512/128, B_);
        gemm_mma<<<fg, 256, GSMEM>>>(Kp,
                                     Wb, Kp, (size_t)0,
                                     Xb, Kp, (size_t)N_ * Kp,
                                     out, N_, (size_t)512 * N_);
    }
}